// round 13
// baseline (speedup 1.0000x reference)
#include <cuda_runtime.h>
#include <math.h>

#define NB 8
#define NS 512
#define NE 64
#define NH 8
#define NW 8
#define SPLITK 4
#define NCHUNK 8
#define ROWS_PB (NS / NCHUNK)       // 64 rows per attn block
#define KEYS_PT (NS / SPLITK)       // 128 keys per thread
#define BBLOCKS 128                 // q-build blocks (32768 rows / 256)
#define TBLOCKS 16                  // transpose rider blocks

// scratch
__device__ float g_q[NB * NH * NS * NW];   // q[bh][s][8]
__device__ float g_ctx[NB * NS * NE];      // attention context [B,S,E]
__device__ float g_WT[NE * NE];            // WT[e*64+o] = Wo[o*64+e]

typedef unsigned long long u64;

__device__ __forceinline__ u64 pk2(float lo, float hi) {
    u64 r; asm("mov.b64 %0,{%1,%2};" : "=l"(r) : "f"(lo), "f"(hi)); return r;
}
__device__ __forceinline__ void unpk2(u64 v, float& lo, float& hi) {
    asm("mov.b64 {%0,%1},%2;" : "=f"(lo), "=f"(hi) : "l"(v));
}
__device__ __forceinline__ void ffma2(u64& d, u64 a, u64 b) {
    asm("fma.rn.f32x2 %0,%1,%2,%0;" : "+l"(d) : "l"(a), "l"(b));
}
__device__ __forceinline__ void fadd2(u64& d, u64 a) {
    asm("add.rn.f32x2 %0,%0,%1;" : "+l"(d) : "l"(a));
}

// ---------------------------------------------------------------------------
// Kernel 0: build q ONCE for every (b,h,s) row + rider transpose of Wo.
//   e[j>=1] = prod_{k<=j} cos(x_k+th_k);  e[0] = prod_{k=1..7} cos(x_k+th_k)
// ---------------------------------------------------------------------------
__global__ __launch_bounds__(256)
void qbuild_kernel(const float* __restrict__ x, const float* __restrict__ theta,
                   const float* __restrict__ Wo)
{
    const int blk = blockIdx.x;
    const int tid = threadIdx.x;

    if (blk >= BBLOCKS) {
        const int i = (blk - BBLOCKS) * 256 + tid;
        const int o = i >> 6, e = i & 63;          // read coalesced
        g_WT[e * NE + o] = Wo[i];
        return;
    }

    float th[NW];
#pragma unroll
    for (int k = 0; k < NW; k++) th[k] = __ldg(&theta[k]);

    // g = row id over (b, s, h) with h fastest -> coalesced x reads
    const int g = blk * 256 + tid;
    const int h = g & 7;
    const int s = (g >> 3) & (NS - 1);
    const int b = g >> 12;

    const float* xp = x + ((b * NS + s) * NE + h * NW);
    const float4 xa = *(const float4*)&xp[0];
    const float4 xb = *(const float4*)&xp[4];
    float c[NW];
    c[0] = __cosf(xa.x + th[0]); c[1] = __cosf(xa.y + th[1]);
    c[2] = __cosf(xa.z + th[2]); c[3] = __cosf(xa.w + th[3]);
    c[4] = __cosf(xb.x + th[4]); c[5] = __cosf(xb.y + th[5]);
    c[6] = __cosf(xb.z + th[6]); c[7] = __cosf(xb.w + th[7]);
    float e[NW];
    float run = c[0];
#pragma unroll
    for (int j = 1; j < NW; j++) { run *= c[j]; e[j] = run; }
    float r = c[NW - 1];
#pragma unroll
    for (int j = NW - 2; j >= 1; j--) r *= c[j];
    e[0] = r;

    float* qp = g_q + (((b * NH + h) * NS) + s) * NW;
    *(float4*)&qp[0] = make_float4(e[0], e[1], e[2], e[3]);
    *(float4*)&qp[4] = make_float4(e[4], e[5], e[6], e[7]);
}

// ---------------------------------------------------------------------------
// Kernel 1: self-attention. Block = (bh, chunk of 64 rows). q slab loaded
//   from g_q (L2-hot). 4 threads/row, interleaved key split. No softmax max
//   pass (|score| <= sqrt(8)). Packed f32x2 FMA.
// ---------------------------------------------------------------------------
__global__ __launch_bounds__(256, 4)
void qattn_kernel()
{
    __shared__ __align__(16) float q[NS][NW];   // 16 KB

    const int blk   = blockIdx.x;
    const int chunk = blk & (NCHUNK - 1);
    const int bh    = blk >> 3;
    const int tid   = threadIdx.x;

    // copy this head's q slab: 4096 floats = 1024 float4, fully coalesced
    {
        const float4* src = (const float4*)(g_q + bh * (NS * NW));
        float4* dst = (float4*)&q[0][0];
#pragma unroll
        for (int i = 0; i < 4; i++)
            dst[tid + 256 * i] = src[tid + 256 * i];
    }
    __syncthreads();

    const int sub = tid & (SPLITK - 1);            // key-split lane
    const int s   = chunk * ROWS_PB + (tid >> 2);  // query row
    const float scale = 0.35355339059327373f;      // 1/sqrt(8)

    u64 qp[4];
    {
        float4 lo4 = *(const float4*)&q[s][0];
        float4 hi4 = *(const float4*)&q[s][4];
        qp[0] = pk2(lo4.x * scale, lo4.y * scale);
        qp[1] = pk2(lo4.z * scale, lo4.w * scale);
        qp[2] = pk2(hi4.x * scale, hi4.y * scale);
        qp[3] = pk2(hi4.z * scale, hi4.w * scale);
    }

    u64 a2[4] = {0ull, 0ull, 0ull, 0ull};
    float l = 0.f;

#pragma unroll 4
    for (int ti = 0; ti < KEYS_PT; ti++) {
        const int t = (ti << 2) + sub;             // interleaved: quad reads 128B
        ulonglong2 kA = *(const ulonglong2*)&q[t][0];
        ulonglong2 kB = *(const ulonglong2*)&q[t][4];

        u64 d2 = 0ull, d2b = 0ull;
        ffma2(d2,  qp[0], kA.x);
        ffma2(d2b, qp[1], kA.y);
        ffma2(d2,  qp[2], kB.x);
        ffma2(d2b, qp[3], kB.y);
        fadd2(d2, d2b);
        float dl, dh; unpk2(d2, dl, dh);

        const float e = __expf(dl + dh);           // safe: |score| <= 2.83
        l += e;
        const u64 ep = pk2(e, e);
        ffma2(a2[0], ep, kA.x);
        ffma2(a2[1], ep, kA.y);
        ffma2(a2[2], ep, kB.x);
        ffma2(a2[3], ep, kB.y);
    }

    // combine 4 split-K partials (sub lanes adjacent in warp)
#pragma unroll
    for (int o = 1; o <= 2; o <<= 1) {
        l += __shfl_xor_sync(0xffffffffu, l, o);
#pragma unroll
        for (int i = 0; i < 4; i++) {
            u64 other = __shfl_xor_sync(0xffffffffu, a2[i], o);
            fadd2(a2[i], other);
        }
    }

    if (sub == 0) {
        const int b = bh >> 3, h = bh & 7;
        const float inv = 1.f / l;
        float o[NW];
#pragma unroll
        for (int i = 0; i < 4; i++) {
            float lo, hi; unpk2(a2[i], lo, hi);
            o[2 * i] = lo * inv; o[2 * i + 1] = hi * inv;
        }
        float* op = g_ctx + ((b * NS + s) * NE + h * NW);
        *(float4*)&op[0] = make_float4(o[0], o[1], o[2], o[3]);
        *(float4*)&op[4] = make_float4(o[4], o[5], o[6], o[7]);
    }
}

// ---------------------------------------------------------------------------
// Kernel 2: out[r][o] = sum_e ctx[r][e] * WT[e][o] + bo[o]   (4096 x 64 x 64)
// 512 blocks x 8 rows. WT staged in smem (L2-hot source). Warp = one row;
// lane owns 2 adjacent outputs (LDS.64 conflict-free, R broadcast), ffma2.
// ---------------------------------------------------------------------------
__global__ __launch_bounds__(256, 4)
void proj_kernel(const float* __restrict__ bo, float* __restrict__ out)
{
    __shared__ __align__(16) float WTs[NE * NE];   // 16 KB
    __shared__ __align__(16) float R[8][NE];       // 2 KB

    const int tid = threadIdx.x;
    const int rowbase = blockIdx.x * 8;

    {
        const float4* src = (const float4*)g_WT;
        float4* dst = (float4*)WTs;
#pragma unroll
        for (int i = 0; i < 4; i++)
            dst[tid + 256 * i] = src[tid + 256 * i];
        if (tid < 128)
            ((float4*)R)[tid] = ((const float4*)(g_ctx + rowbase * NE))[tid];
    }
    __syncthreads();

    const int r  = tid >> 5;            // warp -> row
    const int o0 = (tid & 31) * 2;      // 2 outputs per lane

    u64 acc = *(const u64*)&bo[o0];
    u64 ac2 = 0ull;
#pragma unroll
    for (int e = 0; e < NE; e += 4) {
        const float4 c = *(const float4*)&R[r][e];          // broadcast LDS.128
        const u64 w0 = *(const u64*)&WTs[(e + 0) * NE + o0];
        const u64 w1 = *(const u64*)&WTs[(e + 1) * NE + o0];
        const u64 w2 = *(const u64*)&WTs[(e + 2) * NE + o0];
        const u64 w3 = *(const u64*)&WTs[(e + 3) * NE + o0];
        ffma2(acc, pk2(c.x, c.x), w0);
        ffma2(ac2, pk2(c.y, c.y), w1);
        ffma2(acc, pk2(c.z, c.z), w2);
        ffma2(ac2, pk2(c.w, c.w), w3);
    }
    fadd2(acc, ac2);
    float lo, hi; unpk2(acc, lo, hi);
    float* op = out + (rowbase + r) * NE + o0;
    op[0] = lo; op[1] = hi;
}

extern "C" void kernel_launch(void* const* d_in, const int* in_sizes, int n_in,
                              void* d_out, int out_size)
{
    const float* x     = (const float*)d_in[0];
    const float* theta = (const float*)d_in[1];
    const float* Wo    = (const float*)d_in[2];
    const float* bo    = (const float*)d_in[3];
    float* out = (float*)d_out;

    qbuild_kernel<<<BBLOCKS + TBLOCKS, 256>>>(x, theta, Wo);
    qattn_kernel<<<NB * NH * NCHUNK, 256>>>();
    proj_kernel<<<NB * NS / 8, 256>>>(bo, out);
}